// round 17
// baseline (speedup 1.0000x reference)
#include <cuda_runtime.h>
#include <cuda_fp16.h>
#include <cstdint>

// Problem constants
#define NVERT   20000
#define MTOT    40000          // B * NV
#define CDIM    64
#define NFDIM   128
// Radix-2 split: K' = 3*8*64 = 1536, N' = 128 f * 8 d = 1024
#define KP      1536
#define NP      1024

#define BM      128
#define BNP     64             // CTA tile over N' (per part)
#define BK      16             // 16 halves = 32 B rows
#define NSTAGE  96             // KP / BK; hot loop 93 = 31*3, tail 93..95
#define NPIPE   3

// Precomputed split kernels, n-major: Bp/Bm[n'][k'], n'=f*8+d, k'=(r*8+t)*64+c
//   Bp = (k[u]+k[u+8])/2,  Bm = eps(t,d)*(k[u]-k[u+8])/2,  u=(t-d)&7
__device__ __half g_Bp[(size_t)NP * KP];
__device__ __half g_Bm[(size_t)NP * KP];
__device__ __half g_yh[(size_t)MTOT * CDIM];

__global__ void build_b_split(const float* __restrict__ kern) {
    int tid = blockIdx.x * blockDim.x + threadIdx.x;
    if (tid >= NP * KP) return;
    int k = tid % KP;
    int n = tid / KP;
    int f = n >> 3, d = n & 7;
    int rt = k >> 6, c = k & 63;
    int r = rt >> 3, t = rt & 7;
    int u = (t - d) & 7;
    float klo = kern[((r * 16 + u) * 64 + c) * 128 + f];
    float khi = kern[((r * 16 + u + 8) * 64 + c) * 128 + f];
    g_Bp[tid] = __float2half_rn(0.5f * (klo + khi));
    float km = 0.5f * (klo - khi);
    g_Bm[tid] = __float2half_rn(t >= d ? km : -km);
}

__global__ void conv_y_kernel(const float* __restrict__ y) {
    int tid = blockIdx.x * blockDim.x + threadIdx.x;
    if (tid >= MTOT * CDIM) return;
    g_yh[tid] = __float2half_rn(y[tid]);
}

__device__ __forceinline__ void mma_f16(float c[4], const uint32_t a[4],
                                        uint32_t b0, uint32_t b1) {
    asm volatile(
        "mma.sync.aligned.m16n8k16.row.col.f32.f16.f16.f32 "
        "{%0,%1,%2,%3},{%4,%5,%6,%7},{%8,%9},{%0,%1,%2,%3};"
        : "+f"(c[0]), "+f"(c[1]), "+f"(c[2]), "+f"(c[3])
        : "r"(a[0]), "r"(a[1]), "r"(a[2]), "r"(a[3]), "r"(b0), "r"(b1));
}

__device__ __forceinline__ void ldsm4(uint32_t& r0, uint32_t& r1,
                                      uint32_t& r2, uint32_t& r3, uint32_t addr) {
    asm volatile("ldmatrix.sync.aligned.m8n8.x4.shared.b16 {%0,%1,%2,%3}, [%4];"
                 : "=r"(r0), "=r"(r1), "=r"(r2), "=r"(r3) : "r"(addr));
}

__device__ __forceinline__ void cpasync16(uint32_t dst, const void* src) {
    asm volatile("cp.async.cg.shared.global [%0], [%1], 16;" :: "r"(dst), "l"(src));
}

// 32B rows: 2 x 16B chunks; swizzle chunk ^= (row>>2)&1 -> every 8-row ldsm
// phase and every 8-lane store phase hit 8 distinct 16B bank groups.

struct SmemLayout {
    __half Ap[NPIPE][BM][BK];   // gp tiles  (12 KB)
    __half Am[NPIPE][BM][BK];   // gm tiles  (12 KB)
    __half Bp[NPIPE][BNP][BK];  // kp tiles  ( 6 KB)
    __half Bm[NPIPE][BNP][BK];  // km tiles  ( 6 KB)
};                              // 36864 B; epilogue reuses 32 KB as scratch

#define A_SLOT 4096
#define B_SLOT 2048

__global__ __launch_bounds__(512, 2)
void gemm_kernel(const int* __restrict__ em, const float* __restrict__ bias,
                 float* __restrict__ out) {
    __shared__ __align__(16) SmemLayout sm;

    const int tid  = threadIdx.x;
    const int m0   = blockIdx.y * BM;
    const int n0p  = blockIdx.x * BNP;   // base n' = f*8+d
    const int lane = tid & 31;
    const int warp = tid >> 5;
    const int part = warp >> 3;          // 0 = cyclic (gp*kp), 1 = skew (gm*km)
    const int w8   = warp & 7;
    const int wm   = w8 & 3;             // 4 warps along M (32 rows)
    const int wn   = w8 >> 2;            // 2 warps along N' (32 cols)
    const int lr   = lane >> 2;
    const int lc   = lane & 3;

    // ldmatrix lane decomposition
    const int q   = lane >> 3;
    const int L   = lane & 7;
    const int qr  = (q & 1) * 8 + L;
    const int qhi = q >> 1;

    // Per-warp ldmatrix base addresses (slot 0)
    uint32_t aAddr[2], bAddr[2];
#pragma unroll
    for (int mi = 0; mi < 2; mi++) {
        const int row = wm * 32 + mi * 16 + qr;
        const __half* base = part ? &sm.Am[0][row][0] : &sm.Ap[0][row][0];
        aAddr[mi] = (uint32_t)__cvta_generic_to_shared(base)
                  + (uint32_t)((qhi ^ ((row >> 2) & 1)) << 4);
    }
#pragma unroll
    for (int p = 0; p < 2; p++) {
        const int row = wn * 32 + p * 16 + qr;
        const __half* base = part ? &sm.Bm[0][row][0] : &sm.Bp[0][row][0];
        bAddr[p] = (uint32_t)__cvta_generic_to_shared(base)
                 + (uint32_t)((qhi ^ ((row >> 2) & 1)) << 4);
    }

    // Loader identities.
    // tids 0..255 (= part-0 warps): A rows, 2 threads/row, 16B halves.
    // tids 256..511 (= part-1 warps): B chunks via cp.async.
    const bool isA = tid < 256;
    const int  rowA = tid >> 1;
    const int  halfA = tid & 1;
    const int  chA = halfA ^ ((rowA >> 2) & 1);
    int a_b = 0, a_v = 0;
    if (isA) {
        int m = m0 + rowA;
        if (m >= MTOT) m = 0;
        a_b = (m >= NVERT) ? 1 : 0;
        a_v = m - a_b * NVERT;
    }
    const int qB    = tid - 256;
    const int partB = qB & 1;
    const int halfB = (qB >> 1) & 1;
    const int rowB  = qB >> 2;
    const int chB   = halfB ^ ((rowB >> 2) & 1);
    uint32_t dstB = 0;
    const __half* srcBbase = nullptr;
    if (!isA) {
        const __half* b0 = partB ? &sm.Bm[0][rowB][0] : &sm.Bp[0][rowB][0];
        dstB = (uint32_t)__cvta_generic_to_shared(b0) + (uint32_t)(chB << 4);
        srcBbase = (partB ? g_Bm : g_Bp) + (size_t)(n0p + rowB) * KP + halfB * 8;
    }

    // ---- register-pipelined A gather ----
    uint4 pend0, pend1;   // raw y rows for the next STS stage

    auto lda_issue = [&](int ks) {          // LDG for stage ks -> pend
        if (isA) {
            const int rt  = ks >> 2;
            const int c0  = (ks & 3) << 4;
            const int rti = (rt >> 3) * 16 + (rt & 7);      // r*16 + t
            const int i0  = __ldg(&em[a_v * 48 + rti]);
            const int i1  = __ldg(&em[a_v * 48 + rti + 8]);
            pend0 = *reinterpret_cast<const uint4*>(
                g_yh + (size_t)(a_b * NVERT + i0) * CDIM + c0 + halfA * 8);
            pend1 = *reinterpret_cast<const uint4*>(
                g_yh + (size_t)(a_b * NVERT + i1) * CDIM + c0 + halfA * 8);
        }
    };
    auto lda_store = [&](int slot) {        // pend -> gp/gm tiles
        if (isA) {
            const __half2* h0 = reinterpret_cast<const __half2*>(&pend0);
            const __half2* h1 = reinterpret_cast<const __half2*>(&pend1);
            uint4 P, M;
            __half2* pp = reinterpret_cast<__half2*>(&P);
            __half2* pm = reinterpret_cast<__half2*>(&M);
#pragma unroll
            for (int i = 0; i < 4; i++) {
                pp[i] = __hadd2(h0[i], h1[i]);
                pm[i] = __hsub2(h0[i], h1[i]);
            }
            *reinterpret_cast<uint4*>(&sm.Ap[slot][rowA][chA * 8]) = P;
            *reinterpret_cast<uint4*>(&sm.Am[slot][rowA][chA * 8]) = M;
        }
    };
    auto ldb_async = [&](int ks, int slot) {   // B cp.async + uniform commit
        if (!isA) cpasync16(dstB + (uint32_t)(slot * B_SLOT), srcBbase + ks * BK);
        asm volatile("cp.async.commit_group;");
    };

    float acc[2][4][4];
#pragma unroll
    for (int mi = 0; mi < 2; mi++)
#pragma unroll
        for (int ni = 0; ni < 4; ni++)
#pragma unroll
            for (int j = 0; j < 4; j++) acc[mi][ni][j] = 0.0f;

    auto compute_stage = [&](int slot) {
        const uint32_t ao = (uint32_t)(slot * A_SLOT);
        const uint32_t bo = (uint32_t)(slot * B_SLOT);
        uint32_t a[2][4];
        ldsm4(a[0][0], a[0][1], a[0][2], a[0][3], aAddr[0] + ao);
        ldsm4(a[1][0], a[1][1], a[1][2], a[1][3], aAddr[1] + ao);
#pragma unroll
        for (int p = 0; p < 2; p++) {
            uint32_t b00, b01, b10, b11;
            ldsm4(b00, b01, b10, b11, bAddr[p] + bo);
            mma_f16(acc[0][2 * p],     a[0], b00, b10);
            mma_f16(acc[0][2 * p + 1], a[0], b01, b11);
            mma_f16(acc[1][2 * p],     a[1], b00, b10);
            mma_f16(acc[1][2 * p + 1], a[1], b01, b11);
        }
    };

    // ---- prologue: stages 0,1 loaded directly; pend primed with stage 2 ----
    lda_issue(0); lda_store(0); ldb_async(0, 0);
    lda_issue(1); lda_store(1); ldb_async(1, 1);
    lda_issue(2);

    // ---- hot loop: stages 0..92 (93 = 31*3; slots compile-time) ----
    // Stage s: wait, barrier, STS pend(stage s+2), B-async s+2, LDG s+3, MMA s.
#pragma unroll 1
    for (int ks = 0; ks < NSTAGE - 3; ks += NPIPE) {
#pragma unroll
        for (int j = 0; j < NPIPE; j++) {
            asm volatile("cp.async.wait_group 1;");
            __syncthreads();
            lda_store((j + 2) % NPIPE);
            ldb_async(ks + j + 2, (j + 2) % NPIPE);
            lda_issue(ks + j + 3);          // max stage 95
            compute_stage(j);
        }
    }
    // ---- tail: stages 93, 94, 95 ----
    asm volatile("cp.async.wait_group 1;");
    __syncthreads();
    lda_store(2);                 // stage 95 -> slot 2
    ldb_async(NSTAGE - 1, 2);
    compute_stage(0);             // stage 93
    asm volatile("cp.async.wait_group 1;");
    __syncthreads();
    compute_stage(1);             // stage 94
    asm volatile("cp.async.wait_group 0;");
    __syncthreads();
    compute_stage(2);             // stage 95

    // ---- epilogue: out = Cc + |Cn| (= max over all 16 douts), bias, relu ----
    float* scratch = reinterpret_cast<float*>(&sm);  // 32 KB needed, 36 KB free
    __syncthreads();
    if (part == 1) {
#pragma unroll
        for (int mi = 0; mi < 2; mi++)
#pragma unroll
            for (int ni = 0; ni < 4; ni++)
#pragma unroll
                for (int j = 0; j < 4; j++)
                    scratch[w8 * 1024 + (mi * 16 + ni * 4 + j) * 32 + lane] =
                        acc[mi][ni][j];
    }
    __syncthreads();
    if (part == 0) {
#pragma unroll
        for (int mi = 0; mi < 2; mi++) {
#pragma unroll
            for (int ni = 0; ni < 4; ni++) {
                float v[4];
#pragma unroll
                for (int j = 0; j < 4; j++)
                    v[j] = acc[mi][ni][j] + fabsf(
                        scratch[w8 * 1024 + (mi * 16 + ni * 4 + j) * 32 + lane]);
                float lo = fmaxf(v[0], v[1]);   // row lr,   d = 2lc, 2lc+1
                float hi = fmaxf(v[2], v[3]);   // row lr+8
                lo = fmaxf(lo, __shfl_xor_sync(0xffffffffu, lo, 1));
                lo = fmaxf(lo, __shfl_xor_sync(0xffffffffu, lo, 2));
                hi = fmaxf(hi, __shfl_xor_sync(0xffffffffu, hi, 1));
                hi = fmaxf(hi, __shfl_xor_sync(0xffffffffu, hi, 2));
                if (lc == 0) {
                    const int f = blockIdx.x * 8 + wn * 4 + ni;
                    const float bv = __ldg(&bias[f]);
                    const int r0 = m0 + wm * 32 + mi * 16 + lr;
                    const int r1 = r0 + 8;
                    if (r0 < MTOT) out[r0 * NFDIM + f] = fmaxf(lo + bv, 0.0f);
                    if (r1 < MTOT) out[r1 * NFDIM + f] = fmaxf(hi + bv, 0.0f);
                }
            }
        }
    }
}

extern "C" void kernel_launch(void* const* d_in, const int* in_sizes, int n_in,
                              void* d_out, int out_size) {
    const float* y    = (const float*)d_in[0];
    const int*   em   = (const int*)d_in[1];
    const float* kern = (const float*)d_in[2];
    const float* bias = (const float*)d_in[3];
    float*       out  = (float*)d_out;

    // prep: radix-2 split kernels (kp, eps*km, n-major) + fp16 copy of y
    build_b_split<<<(NP * KP + 255) / 256, 256>>>(kern);
    conv_y_kernel<<<(MTOT * CDIM + 255) / 256, 256>>>(y);

    // fused gather + split-GEMM + combine/max/relu
    dim3 grid(NP / BNP, (MTOT + BM - 1) / BM);   // (16, 313)
    gemm_kernel<<<grid, 512>>>(em, bias, out);
}